// round 15
// baseline (speedup 1.0000x reference)
#include <cuda_runtime.h>
#include <cuda_fp16.h>

// Problem constants
#define KCLS  256
#define NTOT  24000              // BS*Q rows
#define TTOT  2400               // targets
#define NPAIR (TTOT / 2)         // 1200 pairs of 2 targets
#define TPB   128
#define NBLK  2960               // 148 SMs x 10 blocks x 2 = EXACTLY two waves
#define RMAX  9                  // 320 blocks w/ 9 rows + 2640 w/ 8 = 24000

static __device__ __forceinline__ half2 h2_from_f(float f) {
    return *reinterpret_cast<half2*>(&f);
}
static __device__ __forceinline__ float f_from_h2(half2 h) {
    return *reinterpret_cast<float*>(&h);
}

// ---------------------------------------------------------------------------
// Fused kernel: one target-PAIR per thread (9 half2 splat regs), TWO rows per
// inner iteration (restores 4-outputs/iter amortization) at 10 blocks/SM
// (62.5% occ ceiling). Block b owns rows [n0, n0+R), R in {8,9}.
// All geometry x5-scaled (L1 sum = 5*L1; GIoU scale-invariant).
// ---------------------------------------------------------------------------
__global__ __launch_bounds__(TPB, 10) void fused_kernel(
    const float* __restrict__ logits,       // [NTOT, 256]
    const float* __restrict__ pred_boxes,   // [NTOT, 4] cxcywh
    const float* __restrict__ tgt_bbox,     // [TTOT, 4] cxcywh
    const int*   __restrict__ tgt_ids,      // [TTOT]
    float*       __restrict__ out)          // [NTOT, TTOT]
{
    __shared__ float4 s_diff4[RMAX * KCLS / 4];    // 9216 B class-cost table
    __shared__ float4 s_pd[RMAX][2];               //  288 B pred splats

    const int tid = threadIdx.x;
    const int b   = blockIdx.x;
    const int n0  = b * 8 + min(b, 320);
    const int R   = (b < 320) ? 9 : 8;

    // ---- preamble A: class-cost table for R rows: focal(pos-neg)+2
    const float4* lg4 = reinterpret_cast<const float4*>(logits) + n0 * (KCLS / 4);
    for (int i = tid; i < R * (KCLS / 4); i += TPB) {
        float4 x4 = lg4[i];
        float4 o4;
        const float* xs = &x4.x;
        float*       os = &o4.x;
        #pragma unroll
        for (int j = 0; j < 4; j++) {
            float x   = xs[j];
            float ex  = __expf(-x);
            float L   = __logf(1.0f + ex);                // = -log(p)
            float p   = __frcp_rn(1.0f + ex);
            float omp = 1.0f - p;
            float pos = 0.25f * omp * omp * L;            // A(1-p)^2 * -log p
            float neg = 0.75f * p * p * (x + L);          // (1-A) p^2 * -log(1-p)
            os[j] = pos - neg + 2.0f;                     // +2 folds GIoU constant
        }
        s_diff4[i] = o4;
    }

    // ---- preamble B: pred boxes -> x5-scaled half2 splats
    if (tid < R) {
        float4 pb = reinterpret_cast<const float4*>(pred_boxes)[n0 + tid];
        pb.x *= 5.0f; pb.y *= 5.0f; pb.z *= 5.0f; pb.w *= 5.0f;
        s_pd[tid][0] = make_float4(f_from_h2(__float2half2_rn(pb.x)),
                                   f_from_h2(__float2half2_rn(pb.y)),
                                   f_from_h2(__float2half2_rn(pb.z)),
                                   f_from_h2(__float2half2_rn(pb.w)));
        s_pd[tid][1] = make_float4(f_from_h2(__float2half2_rn(pb.x - 0.5f * pb.z)),
                                   f_from_h2(__float2half2_rn(pb.y - 0.5f * pb.w)),
                                   f_from_h2(__float2half2_rn(pb.x + 0.5f * pb.z)),
                                   f_from_h2(__float2half2_rn(pb.y + 0.5f * pb.w)));
    }
    __syncthreads();

    const float* s_diff = reinterpret_cast<const float*>(s_diff4);
    const half2 zero2 = __float2half2_rn(0.0f);
    const half2 m2    = __float2half2_rn(-2.0f);

    for (int pp = tid; pp < NPAIR; pp += TPB) {
        // ---- one target pair: ids + x5-scaled half2 splats (9 regs) ----
        int2 id2 = reinterpret_cast<const int2*>(tgt_ids)[pp];
        float4 a  = reinterpret_cast<const float4*>(tgt_bbox)[2 * pp];
        float4 bx = reinterpret_cast<const float4*>(tgt_bbox)[2 * pp + 1];
        a.x *= 5.0f;  a.y *= 5.0f;  a.z *= 5.0f;  a.w *= 5.0f;
        bx.x *= 5.0f; bx.y *= 5.0f; bx.z *= 5.0f; bx.w *= 5.0f;
        const half2 tcx2 = __floats2half2_rn(a.x, bx.x);
        const half2 tcy2 = __floats2half2_rn(a.y, bx.y);
        const half2 tw2  = __floats2half2_rn(a.z, bx.z);
        const half2 th2  = __floats2half2_rn(a.w, bx.w);
        const half2 tx02 = __floats2half2_rn(a.x - 0.5f * a.z, bx.x - 0.5f * bx.z);
        const half2 ty02 = __floats2half2_rn(a.y - 0.5f * a.w, bx.y - 0.5f * bx.w);
        const half2 tx12 = __floats2half2_rn(a.x + 0.5f * a.z, bx.x + 0.5f * bx.z);
        const half2 ty12 = __floats2half2_rn(a.y + 0.5f * a.w, bx.y + 0.5f * bx.w);
        const half2 ta2  = __floats2half2_rn(a.z * a.w,        bx.z * bx.w);

        // single-row evaluation (inlined twice per pair-iteration)
        auto eval_row = [&](int r) {
            const float4 f0 = s_pd[r][0];                 // 2x LDS.128 broadcast
            const float4 f1 = s_pd[r][1];
            const half2 pcx2  = h2_from_f(f0.x);
            const half2 pcy2  = h2_from_f(f0.y);
            const half2 pw2   = h2_from_f(f0.z);
            const half2 ph2   = h2_from_f(f0.w);
            const half2 px0_2 = h2_from_f(f1.x);
            const half2 py0_2 = h2_from_f(f1.y);
            const half2 px1_2 = h2_from_f(f1.z);
            const half2 py1_2 = h2_from_f(f1.w);
            const half2 pa_2  = __hmul2(pw2, ph2);
            const float* __restrict__ drow = s_diff + r * KCLS;

            half2 l15 = __hadd2(
                __hadd2(__habs2(__hsub2(pcx2, tcx2)),
                        __habs2(__hsub2(pcy2, tcy2))),
                __hadd2(__habs2(__hsub2(pw2,  tw2)),
                        __habs2(__hsub2(ph2,  th2))));
            half2 diw = __hsub2(__hmin2(px1_2, tx12), __hmax2(px0_2, tx02));
            half2 dih = __hsub2(__hmin2(py1_2, ty12), __hmax2(py0_2, ty02));
            half2 inter = __hmul2(__hmax2(diw, zero2), __hmax2(dih, zero2));
            half2 uni   = __hsub2(__hadd2(pa_2, ta2), inter);
            half2 ew  = __hsub2(__hadd2(pw2, tw2), diw);
            half2 eh  = __hsub2(__hadd2(ph2, th2), dih);
            half2 ea  = __hmul2(ew, eh);
            half2 tm  = __hfma2(uni, h2rcp(ea), __hmul2(inter, h2rcp(uni)));
            half2 h = __hfma2(tm, m2, l15);               // 5*L1 - 2*(i/u+u/e)

            float2 res;
            res.x = __low2float(h)  + drow[id2.x];        // + (diff+2) fp32
            res.y = __high2float(h) + drow[id2.y];
            reinterpret_cast<float2*>(out)[(n0 + r) * NPAIR + pp] = res;
        };

        // ---- rows 0..7 as 4 row-pairs (4 outputs per iteration) ----
        #pragma unroll 1
        for (int p = 0; p < 4; p++) {
            eval_row(2 * p);
            eval_row(2 * p + 1);
        }
        // ---- tail row 8 only when R == 9 ----
        if (R == 9)
            eval_row(8);
    }
}

// ---------------------------------------------------------------------------
extern "C" void kernel_launch(void* const* d_in, const int* in_sizes, int n_in,
                              void* d_out, int out_size)
{
    const float* pred_logits = (const float*)d_in[0];  // [16,1500,256]
    const float* pred_boxes  = (const float*)d_in[1];  // [16,1500,4]
    const float* tgt_bbox    = (const float*)d_in[2];  // [2400,4]
    const int*   tgt_ids     = (const int*)  d_in[3];  // [2400]
    float*       out         = (float*)d_out;          // [16,1500,2400]

    fused_kernel<<<NBLK, TPB>>>(pred_logits, pred_boxes, tgt_bbox,
                                tgt_ids, out);
}

// round 16
// speedup vs baseline: 1.0390x; 1.0390x over previous
#include <cuda_runtime.h>
#include <cuda_fp16.h>

// Problem constants
#define KCLS  256
#define NTOT  24000              // BS*Q rows
#define TTOT  2400               // targets
#define NQUAD (TTOT / 4)         // 600 quads of 4 targets
#define TPB   128
#define RFIX  9                  // uniform rows per block (compile-time)
#define NBLK  2667               // 2666 blocks x 9 rows + 1 block x 6 rows
#define RMAX  9

static __device__ __forceinline__ half2 h2_from_f(float f) {
    return *reinterpret_cast<half2*>(&f);
}
static __device__ __forceinline__ float f_from_h2(half2 h) {
    return *reinterpret_cast<float*>(&h);
}

// ---------------------------------------------------------------------------
// Fused kernel (R7 body): quad-per-thread, x5-scaled half2 geometry,
// fp32 class table + scalar gathers. Uniform R=9 lets the hot path use a
// partially-unrolled row loop (unroll 3) so ptxas can batch LDS.128 across
// rows and interleave 3 independent compute chains (hides 29-cyc LDS lat).
// ---------------------------------------------------------------------------
__global__ __launch_bounds__(TPB, 9) void fused_kernel(
    const float* __restrict__ logits,       // [NTOT, 256]
    const float* __restrict__ pred_boxes,   // [NTOT, 4] cxcywh
    const float* __restrict__ tgt_bbox,     // [TTOT, 4] cxcywh
    const int*   __restrict__ tgt_ids,      // [TTOT]
    float*       __restrict__ out)          // [NTOT, TTOT]
{
    __shared__ float4 s_diff4[RMAX * KCLS / 4];    // 9216 B class-cost table
    __shared__ float4 s_pd[RMAX][2];               //  288 B pred splats

    const int tid = threadIdx.x;
    const int b   = blockIdx.x;
    const int n0  = b * RFIX;
    const int R   = min(RFIX, NTOT - n0);          // 9 everywhere, 6 for b=2666

    // ---- preamble A: class-cost table for R rows: focal(pos-neg)+2
    const float4* lg4 = reinterpret_cast<const float4*>(logits) + n0 * (KCLS / 4);
    for (int i = tid; i < R * (KCLS / 4); i += TPB) {
        float4 x4 = lg4[i];
        float4 o4;
        const float* xs = &x4.x;
        float*       os = &o4.x;
        #pragma unroll
        for (int j = 0; j < 4; j++) {
            float x   = xs[j];
            float ex  = __expf(-x);
            float L   = __logf(1.0f + ex);                // = -log(p)
            float p   = __frcp_rn(1.0f + ex);
            float omp = 1.0f - p;
            float pos = 0.25f * omp * omp * L;            // A(1-p)^2 * -log p
            float neg = 0.75f * p * p * (x + L);          // (1-A) p^2 * -log(1-p)
            os[j] = pos - neg + 2.0f;                     // +2 folds GIoU constant
        }
        s_diff4[i] = o4;
    }

    // ---- preamble B: pred boxes -> x5-scaled half2 splats
    if (tid < R) {
        float4 pb = reinterpret_cast<const float4*>(pred_boxes)[n0 + tid];
        pb.x *= 5.0f; pb.y *= 5.0f; pb.z *= 5.0f; pb.w *= 5.0f;
        s_pd[tid][0] = make_float4(f_from_h2(__float2half2_rn(pb.x)),
                                   f_from_h2(__float2half2_rn(pb.y)),
                                   f_from_h2(__float2half2_rn(pb.z)),
                                   f_from_h2(__float2half2_rn(pb.w)));
        s_pd[tid][1] = make_float4(f_from_h2(__float2half2_rn(pb.x - 0.5f * pb.z)),
                                   f_from_h2(__float2half2_rn(pb.y - 0.5f * pb.w)),
                                   f_from_h2(__float2half2_rn(pb.x + 0.5f * pb.z)),
                                   f_from_h2(__float2half2_rn(pb.y + 0.5f * pb.w)));
    }
    __syncthreads();

    const float* s_diff = reinterpret_cast<const float*>(s_diff4);
    const half2 zero2 = __float2half2_rn(0.0f);
    const half2 m2    = __float2half2_rn(-2.0f);

    for (int q = tid; q < NQUAD; q += TPB) {
        // ---- load + derive 4 targets (x5-scaled, once per quad) ----
        int4 id4 = reinterpret_cast<const int4*>(tgt_ids)[q];
        const int ids[4] = {id4.x, id4.y, id4.z, id4.w};

        half2 tcx2[2], tcy2[2], tw2[2], th2[2];
        half2 tx0_2[2], ty0_2[2], tx1_2[2], ty1_2[2], ta_2[2];
        #pragma unroll
        for (int g = 0; g < 2; g++) {
            float4 a  = reinterpret_cast<const float4*>(tgt_bbox)[4 * q + 2 * g];
            float4 bx = reinterpret_cast<const float4*>(tgt_bbox)[4 * q + 2 * g + 1];
            a.x *= 5.0f;  a.y *= 5.0f;  a.z *= 5.0f;  a.w *= 5.0f;
            bx.x *= 5.0f; bx.y *= 5.0f; bx.z *= 5.0f; bx.w *= 5.0f;
            tcx2[g]  = __floats2half2_rn(a.x, bx.x);
            tcy2[g]  = __floats2half2_rn(a.y, bx.y);
            tw2[g]   = __floats2half2_rn(a.z, bx.z);
            th2[g]   = __floats2half2_rn(a.w, bx.w);
            tx0_2[g] = __floats2half2_rn(a.x - 0.5f * a.z, bx.x - 0.5f * bx.z);
            ty0_2[g] = __floats2half2_rn(a.y - 0.5f * a.w, bx.y - 0.5f * bx.w);
            tx1_2[g] = __floats2half2_rn(a.x + 0.5f * a.z, bx.x + 0.5f * bx.z);
            ty1_2[g] = __floats2half2_rn(a.y + 0.5f * a.w, bx.y + 0.5f * bx.w);
            ta_2[g]  = __floats2half2_rn(a.z * a.w,        bx.z * bx.w);
        }

        auto eval_row = [&](int r) {
            const float4 f0 = s_pd[r][0];                 // 2x LDS.128 broadcast
            const float4 f1 = s_pd[r][1];
            const half2 pcx2  = h2_from_f(f0.x);
            const half2 pcy2  = h2_from_f(f0.y);
            const half2 pw2   = h2_from_f(f0.z);
            const half2 ph2   = h2_from_f(f0.w);
            const half2 px0_2 = h2_from_f(f1.x);
            const half2 py0_2 = h2_from_f(f1.y);
            const half2 px1_2 = h2_from_f(f1.z);
            const half2 py1_2 = h2_from_f(f1.w);
            const half2 pa_2  = __hmul2(pw2, ph2);
            const float* __restrict__ drow = s_diff + r * KCLS;

            float hv[4];
            #pragma unroll
            for (int g = 0; g < 2; g++) {
                half2 l15 = __hadd2(
                    __hadd2(__habs2(__hsub2(pcx2, tcx2[g])),
                            __habs2(__hsub2(pcy2, tcy2[g]))),
                    __hadd2(__habs2(__hsub2(pw2,  tw2[g])),
                            __habs2(__hsub2(ph2,  th2[g]))));
                half2 diw = __hsub2(__hmin2(px1_2, tx1_2[g]),
                                    __hmax2(px0_2, tx0_2[g]));
                half2 dih = __hsub2(__hmin2(py1_2, ty1_2[g]),
                                    __hmax2(py0_2, ty0_2[g]));
                half2 inter = __hmul2(__hmax2(diw, zero2), __hmax2(dih, zero2));
                half2 uni   = __hsub2(__hadd2(pa_2, ta_2[g]), inter);
                half2 ew  = __hsub2(__hadd2(pw2, tw2[g]), diw);
                half2 eh  = __hsub2(__hadd2(ph2, th2[g]), dih);
                half2 ea  = __hmul2(ew, eh);
                half2 tm  = __hfma2(uni, h2rcp(ea), __hmul2(inter, h2rcp(uni)));
                half2 h   = __hfma2(tm, m2, l15);         // 5*L1 - 2*(i/u+u/e)
                hv[2 * g]     = __low2float(h);
                hv[2 * g + 1] = __high2float(h);
            }

            float c[4];
            #pragma unroll
            for (int j = 0; j < 4; j++)
                c[j] = hv[j] + drow[ids[j]];              // + (diff+2) fp32
            reinterpret_cast<float4*>(out)[(n0 + r) * NQUAD + q] =
                make_float4(c[0], c[1], c[2], c[3]);
        };

        if (R == RFIX) {
            // hot path: compile-time 9 rows, unroll 3 -> ptxas batches LDS
            #pragma unroll 3
            for (int r = 0; r < RFIX; r++)
                eval_row(r);
        } else {
            // last block only (6 rows)
            for (int r = 0; r < R; r++)
                eval_row(r);
        }
    }
}

// ---------------------------------------------------------------------------
extern "C" void kernel_launch(void* const* d_in, const int* in_sizes, int n_in,
                              void* d_out, int out_size)
{
    const float* pred_logits = (const float*)d_in[0];  // [16,1500,256]
    const float* pred_boxes  = (const float*)d_in[1];  // [16,1500,4]
    const float* tgt_bbox    = (const float*)d_in[2];  // [2400,4]
    const int*   tgt_ids     = (const int*)  d_in[3];  // [2400]
    float*       out         = (float*)d_out;          // [16,1500,2400]

    fused_kernel<<<NBLK, TPB>>>(pred_logits, pred_boxes, tgt_bbox,
                                tgt_ids, out);
}

// round 17
// speedup vs baseline: 1.0639x; 1.0240x over previous
#include <cuda_runtime.h>
#include <cuda_fp16.h>

// Problem constants
#define KCLS  256
#define NTOT  24000              // BS*Q rows
#define TTOT  2400               // targets
#define NQUAD (TTOT / 4)         // 600 quads of 4 targets
#define TPB   128
#define NBLK  2664               // 148 SMs x 9 blocks x 2 = EXACTLY two waves
#define RMAX  10                 // 24 blocks w/ 10 rows + 2640 w/ 9 = 24000

// All geometry pre-scaled by 5: L1 sum yields 5*L1 directly; GIoU is
// scale-invariant (ratios of areas), so the same scaled splats serve both.
struct __align__(16) PredPk {    // 9 half2 packed in 3 float4 (x5-scaled)
    float4 f0;   // pcx2, pcy2, pw2, ph2
    float4 f1;   // px0_2, py0_2, px1_2, py1_2
    float4 f2;   // pa_2 (=25*w*h), pad...
};

static __device__ __forceinline__ half2 h2_from_f(float f) {
    return *reinterpret_cast<half2*>(&f);
}
static __device__ __forceinline__ float f_from_h2(half2 h) {
    return *reinterpret_cast<float*>(&h);
}

__global__ __launch_bounds__(TPB, 9) void fused_kernel(
    const float* __restrict__ logits,       // [NTOT, 256]
    const float* __restrict__ pred_boxes,   // [NTOT, 4] cxcywh
    const float* __restrict__ tgt_bbox,     // [TTOT, 4] cxcywh
    const int*   __restrict__ tgt_ids,      // [TTOT]
    float*       __restrict__ out)          // [NTOT, TTOT]
{
    __shared__ float4 s_diff4[RMAX * KCLS / 4];    // 10240 B
    __shared__ PredPk s_pd[RMAX];                  //   480 B

    const int tid = threadIdx.x;
    const int b   = blockIdx.x;
    const int n0  = b * 9 + min(b, 24);
    const int R   = (b < 24) ? 10 : 9;

    // ---- preamble A: class-cost table for R rows: focal(pos-neg)+2
    const float4* lg4 = reinterpret_cast<const float4*>(logits) + n0 * (KCLS / 4);
    for (int i = tid; i < R * (KCLS / 4); i += TPB) {
        float4 x4 = lg4[i];
        float4 o4;
        const float* xs = &x4.x;
        float*       os = &o4.x;
        #pragma unroll
        for (int j = 0; j < 4; j++) {
            float x   = xs[j];
            float ex  = __expf(-x);
            float L   = __logf(1.0f + ex);                // = -log(p)
            float p   = __frcp_rn(1.0f + ex);
            float omp = 1.0f - p;
            float pos = 0.25f * omp * omp * L;            // A(1-p)^2 * -log p
            float neg = 0.75f * p * p * (x + L);          // (1-A) p^2 * -log(1-p)
            os[j] = pos - neg + 2.0f;                     // +2 folds GIoU constant
        }
        s_diff4[i] = o4;
    }

    // ---- preamble B: pred boxes -> x5-scaled half2 splats
    if (tid < R) {
        float4 pb = reinterpret_cast<const float4*>(pred_boxes)[n0 + tid];
        pb.x *= 5.0f; pb.y *= 5.0f; pb.z *= 5.0f; pb.w *= 5.0f;
        PredPk pk;
        pk.f0 = make_float4(f_from_h2(__float2half2_rn(pb.x)),
                            f_from_h2(__float2half2_rn(pb.y)),
                            f_from_h2(__float2half2_rn(pb.z)),
                            f_from_h2(__float2half2_rn(pb.w)));
        pk.f1 = make_float4(f_from_h2(__float2half2_rn(pb.x - 0.5f * pb.z)),
                            f_from_h2(__float2half2_rn(pb.y - 0.5f * pb.w)),
                            f_from_h2(__float2half2_rn(pb.x + 0.5f * pb.z)),
                            f_from_h2(__float2half2_rn(pb.y + 0.5f * pb.w)));
        pk.f2 = make_float4(f_from_h2(__float2half2_rn(pb.z * pb.w)),
                            0.0f, 0.0f, 0.0f);
        s_pd[tid] = pk;
    }
    __syncthreads();

    const float* s_diff = reinterpret_cast<const float*>(s_diff4);
    const half2 zero2 = __float2half2_rn(0.0f);
    const half2 m2    = __float2half2_rn(-2.0f);
    const half2 mh2   = __float2half2_rn(-0.5f);
    const half2 ph2c  = __float2half2_rn(0.5f);

    for (int q = tid; q < NQUAD; q += TPB) {
        // ---- load + derive 4 targets (x5-scaled; xyxy derived in half2) ----
        int4 id4 = reinterpret_cast<const int4*>(tgt_ids)[q];

        half2 tcx2[2], tcy2[2], tw2[2], th2[2];
        half2 tx0_2[2], ty0_2[2], tx1_2[2], ty1_2[2], ta_2[2];
        #pragma unroll
        for (int g = 0; g < 2; g++) {
            float4 a  = reinterpret_cast<const float4*>(tgt_bbox)[4 * q + 2 * g];
            float4 bx = reinterpret_cast<const float4*>(tgt_bbox)[4 * q + 2 * g + 1];
            half2 cx = __floats2half2_rn(a.x * 5.0f, bx.x * 5.0f);
            half2 cy = __floats2half2_rn(a.y * 5.0f, bx.y * 5.0f);
            half2 w  = __floats2half2_rn(a.z * 5.0f, bx.z * 5.0f);
            half2 h  = __floats2half2_rn(a.w * 5.0f, bx.w * 5.0f);
            tcx2[g]  = cx;  tcy2[g] = cy;  tw2[g] = w;  th2[g] = h;
            tx0_2[g] = __hfma2(w, mh2,  cx);              // cx - w/2
            ty0_2[g] = __hfma2(h, mh2,  cy);
            tx1_2[g] = __hfma2(w, ph2c, cx);              // cx + w/2
            ty1_2[g] = __hfma2(h, ph2c, cy);
            ta_2[g]  = __hmul2(w, h);
        }

        #pragma unroll 1
        for (int r = 0; r < R; r++) {
            const float4 f0 = s_pd[r].f0;
            const float4 f1 = s_pd[r].f1;
            const half2 pcx2  = h2_from_f(f0.x);
            const half2 pcy2  = h2_from_f(f0.y);
            const half2 pw2   = h2_from_f(f0.z);
            const half2 ph2   = h2_from_f(f0.w);
            const half2 px0_2 = h2_from_f(f1.x);
            const half2 py0_2 = h2_from_f(f1.y);
            const half2 px1_2 = h2_from_f(f1.z);
            const half2 py1_2 = h2_from_f(f1.w);
            const half2 pa_2  = h2_from_f(s_pd[r].f2.x);
            const float* __restrict__ drow = s_diff + r * KCLS;

            float hv[4];
            #pragma unroll
            for (int g = 0; g < 2; g++) {
                // ---- 5*L1 directly from x5-scaled coords (half2, 2 targets)
                half2 l15 = __hadd2(
                    __hadd2(__habs2(__hsub2(pcx2, tcx2[g])),
                            __habs2(__hsub2(pcy2, tcy2[g]))),
                    __hadd2(__habs2(__hsub2(pw2,  tw2[g])),
                            __habs2(__hsub2(ph2,  th2[g]))));
                // ---- GIoU (scale-invariant; same x5 splats) ----
                half2 diw = __hsub2(__hmin2(px1_2, tx1_2[g]),
                                    __hmax2(px0_2, tx0_2[g]));
                half2 dih = __hsub2(__hmin2(py1_2, ty1_2[g]),
                                    __hmax2(py0_2, ty0_2[g]));
                half2 inter = __hmul2(__hmax2(diw, zero2), __hmax2(dih, zero2));
                half2 uni   = __hsub2(__hadd2(pa_2, ta_2[g]), inter);
                half2 ew  = __hsub2(__hadd2(pw2, tw2[g]), diw);
                half2 eh  = __hsub2(__hadd2(ph2, th2[g]), dih);
                half2 ea  = __hmul2(ew, eh);
                half2 tm  = __hfma2(uni, h2rcp(ea), __hmul2(inter, h2rcp(uni)));
                // ---- fused: h = 5*L1 - 2*(i/u + u/e)  (one HFMA2, 2 targets)
                half2 h = __hfma2(tm, m2, l15);
                hv[2 * g]     = __low2float(h);
                hv[2 * g + 1] = __high2float(h);
            }

            float c[4];
            c[0] = hv[0] + drow[id4.x];                   // + (diff+2) fp32
            c[1] = hv[1] + drow[id4.y];
            c[2] = hv[2] + drow[id4.z];
            c[3] = hv[3] + drow[id4.w];
            reinterpret_cast<float4*>(out)[(n0 + r) * NQUAD + q] =
                make_float4(c[0], c[1], c[2], c[3]);
        }
    }
}

// ---------------------------------------------------------------------------
extern "C" void kernel_launch(void* const* d_in, const int* in_sizes, int n_in,
                              void* d_out, int out_size)
{
    const float* pred_logits = (const float*)d_in[0];  // [16,1500,256]
    const float* pred_boxes  = (const float*)d_in[1];  // [16,1500,4]
    const float* tgt_bbox    = (const float*)d_in[2];  // [2400,4]
    const int*   tgt_ids     = (const int*)  d_in[3];  // [2400]
    float*       out         = (float*)d_out;          // [16,1500,2400]

    fused_kernel<<<NBLK, TPB>>>(pred_logits, pred_boxes, tgt_bbox,
                                tgt_ids, out);
}